// round 14
// baseline (speedup 1.0000x reference)
#include <cuda_runtime.h>
#include <cuda_fp16.h>
#include <math.h>

#define NU 100000
#define NI 50000
#define DD 64
#define EPSV 1e-12f
#define MAXH 3200000
#define MAXI 3000000

typedef long long ll;

static constexpr ll S  = (ll)NU * DD;
static constexpr ll SI = (ll)NI * DD;

// fp32 scratch: 4 accumulators + v vector
static constexpr ll ACC0 = 0;
static constexpr ll ACC1 = 1 * S;
static constexpr ll ACC2 = 2 * S;
static constexpr ll ACCS = 3 * S;
static constexpr ll VOFF = 4 * S;
static constexpr ll TOT32 = VOFF + 64;
__device__ float g_buf[TOT32];

// fp16 gather-format scratch
static constexpr ll XG0 = 0;
static constexpr ll XG1 = 1 * S;
static constexpr ll XG2 = 2 * S;
static constexpr ll XGS = 3 * S;
static constexpr ll XT0 = 4 * S;
static constexpr ll XT1 = 5 * S;
static constexpr ll XT2 = 6 * S;
static constexpr ll XUS = 7 * S;
static constexpr ll XMIX = 8 * S;
static constexpr ll XIT  = 9 * S;
static constexpr ll XITA = 9 * S + SI;
static constexpr ll TOT16 = 9 * S + 2 * SI;
__device__ __half g_h[TOT16];

// CSR scratch
static constexpr int OFFLEN = 4 * (NU + 1) + (NI + 1);
__device__ int  g_off[OFFLEN];
__device__ int  g_cnt[OFFLEN];
__device__ int  g_rank[3 * (ll)MAXH + 2 * (ll)MAXI];
__device__ int2 g_pair[3 * (ll)MAXH + 2 * (ll)MAXI];

struct Build5 {
    const int* row[5]; const int* col[5]; const float* val[5];
    int* rank[5]; int* cnt[5]; const int* off[5]; int2* pair[5]; int nnz[5];
};
struct Spmm5 { const int* off[5]; const int2* pair[5];
               const __half* x[5]; __half* y[5]; float* acc[5]; };

// ---------------------------------------------------------------------------
__device__ __forceinline__ float warp_sum(float v) {
#pragma unroll
    for (int o = 16; o > 0; o >>= 1) v += __shfl_xor_sync(0xFFFFFFFFu, v, o);
    return v;
}

// ---------------------------------------------------------------------------
__global__ void zero_int_kernel(int* p, int n) {
    int i = blockIdx.x * blockDim.x + threadIdx.x;
    if (i < n) p[i] = 0;
}

// fused 5-region histogram, 4 edges/thread, stores per-edge rank (R9 shape)
__global__ void hist5_kernel(Build5 b, int bpr) {
    int region = blockIdx.x / bpr;
    int bb = blockIdx.x - region * bpr;
    int nnz = b.nnz[region];
    const int* __restrict__ row = b.row[region];
    int* __restrict__ rank = b.rank[region];
    int* cnt = b.cnt[region];
    int i = (bb * 256 + threadIdx.x) * 4;
    if (i + 3 < nnz) {
        int4 r = *(const int4*)(row + i);
        int k0 = atomicAdd(cnt + r.x, 1);
        int k1 = atomicAdd(cnt + r.y, 1);
        int k2 = atomicAdd(cnt + r.z, 1);
        int k3 = atomicAdd(cnt + r.w, 1);
        *(int4*)(rank + i) = make_int4(k0, k1, k2, k3);
    } else {
        for (int j = i; j < nnz; ++j) rank[j] = atomicAdd(cnt + __ldg(row + j), 1);
    }
}

// one block per region; chunked exclusive scan of counts -> off
__global__ void scan_kernel() {
    int region = blockIdx.x;
    int n = (region == 4) ? NI : NU;
    int base = region * (NU + 1);
    int* cnt = g_cnt + base;
    int* off = g_off + base;
    const int T = 1024;
    int t = threadIdx.x;
    int chunk = (n + T - 1) / T;
    int lo = t * chunk;
    int hi = lo + chunk; if (hi > n) hi = n;
    int sum = 0;
    for (int i = lo; i < hi; ++i) sum += cnt[i];

    __shared__ int ws[32];
    int lane = t & 31, wid = t >> 5;
    int x = sum;
#pragma unroll
    for (int o = 1; o < 32; o <<= 1) {
        int y = __shfl_up_sync(0xFFFFFFFFu, x, o);
        if (lane >= o) x += y;
    }
    if (lane == 31) ws[wid] = x;
    __syncthreads();
    if (t < 32) {
        int y = ws[t];
#pragma unroll
        for (int o = 1; o < 32; o <<= 1) {
            int z = __shfl_up_sync(0xFFFFFFFFu, y, o);
            if (t >= o) y += z;
        }
        ws[t] = y;
    }
    __syncthreads();
    int pre = x - sum + ((wid > 0) ? ws[wid - 1] : 0);
    if (t == T - 1) off[n] = pre + sum;
    int run = pre;
    for (int i = lo; i < hi; ++i) {
        int v = cnt[i];
        off[i] = run;
        run += v;
    }
}

// fused 5-region scatter, 4 edges/thread, atomic-free via rank.
// Column index stored PRE-SCALED by 32 (half2 units per row) for the SpMM.
__global__ void scat5_kernel(Build5 b, int bpr) {
    int region = blockIdx.x / bpr;
    int bb = blockIdx.x - region * bpr;
    int nnz = b.nnz[region];
    const int* __restrict__ row = b.row[region];
    const int* __restrict__ col = b.col[region];
    const float* __restrict__ val = b.val[region];
    const int* __restrict__ rank = b.rank[region];
    const int* __restrict__ off = b.off[region];
    int2* __restrict__ pair = b.pair[region];
    int i = (bb * 256 + threadIdx.x) * 4;
    if (i + 3 < nnz) {
        int4 r = *(const int4*)(row + i);
        int4 c = *(const int4*)(col + i);
        float4 v = *(const float4*)(val + i);
        int4 k = *(const int4*)(rank + i);
        pair[__ldg(off + r.x) + k.x] = make_int2(c.x << 5, __float_as_int(v.x));
        pair[__ldg(off + r.y) + k.y] = make_int2(c.y << 5, __float_as_int(v.y));
        pair[__ldg(off + r.z) + k.z] = make_int2(c.z << 5, __float_as_int(v.z));
        pair[__ldg(off + r.w) + k.w] = make_int2(c.w << 5, __float_as_int(v.w));
    } else {
        for (int j = i; j < nnz; ++j) {
            pair[__ldg(off + __ldg(row + j)) + __ldg(rank + j)] =
                make_int2(__ldg(col + j) << 5, __float_as_int(__ldg(val + j)));
        }
    }
}

// Fused 5-region CSR SpMM: one warp per row, cooperative pair loading via shfl,
// fp16 gathers with pre-scaled column offsets, fp32 accumulate, fused l2norm-acc.
__global__ void spmm5_kernel(Spmm5 a) {
    ll gw = ((ll)blockIdx.x * blockDim.x + threadIdx.x) >> 5;
    int lane = threadIdx.x & 31;
    int region, row;
    if (gw < NU)                { region = 0; row = (int)gw; }
    else if (gw < 2 * NU)       { region = 1; row = (int)(gw - NU); }
    else if (gw < 3 * NU)       { region = 2; row = (int)(gw - 2 * NU); }
    else if (gw < 3 * NU + NI)  { region = 3; row = (int)(gw - 3 * NU); }
    else if (gw < 4 * NU + NI)  { region = 4; row = (int)(gw - 3 * NU - NI); }
    else return;

    const int* off = a.off[region];
    const int2* __restrict__ pair = a.pair[region];
    const __half2* __restrict__ x2 = (const __half2*)a.x[region];
    int s = __ldg(off + row), e = __ldg(off + row + 1);
    float ax = 0.f, ay = 0.f;
    int base = s;
    while (e - base >= 32) {
        int2 myp = __ldg(pair + base + lane);
#pragma unroll 8
        for (int j = 0; j < 32; ++j) {
            int coff = __shfl_sync(0xFFFFFFFFu, myp.x, j);
            float v = __int_as_float(__shfl_sync(0xFFFFFFFFu, myp.y, j));
            float2 f = __half22float2(__ldg(x2 + coff + lane));
            ax = fmaf(v, f.x, ax); ay = fmaf(v, f.y, ay);
        }
        base += 32;
    }
    int rem = e - base;
    if (rem > 0) {
        int2 myp = (lane < rem) ? __ldg(pair + base + lane) : make_int2(0, 0);
        for (int j = 0; j < rem; ++j) {
            int coff = __shfl_sync(0xFFFFFFFFu, myp.x, j);
            float v = __int_as_float(__shfl_sync(0xFFFFFFFFu, myp.y, j));
            float2 f = __half22float2(__ldg(x2 + coff + lane));
            ax = fmaf(v, f.x, ax); ay = fmaf(v, f.y, ay);
        }
    }

    __half* y16 = a.y[region];
    if (y16) ((__half2*)(y16 + (ll)row * DD))[lane] = __floats2half2_rn(ax, ay);
    float ss = warp_sum(ax * ax + ay * ay);
    float sc = 1.f / fmaxf(sqrtf(ss), EPSV);
    float* acc = a.acc[region];
    ll b2 = (ll)row * DD + lane * 2;
    float2 av = *(const float2*)(acc + b2);
    av.x = fmaf(ax, sc, av.x);
    av.y = fmaf(ay, sc, av.y);
    *(float2*)(acc + b2) = av;
}

// v[d] = sum_j att_mat[d][j] * att_agg[j]
__global__ void compute_v_kernel(const float* __restrict__ att_mat,
                                 const float* __restrict__ att_agg) {
    int d = threadIdx.x;
    float s = 0.f;
#pragma unroll
    for (int j = 0; j < DD; ++j) s = fmaf(att_mat[d * DD + j], att_agg[j], s);
    g_buf[VOFF + d] = s;
}

__global__ void item_h_kernel(const float* __restrict__ src, __half* __restrict__ dst, int n2) {
    int i = blockIdx.x * blockDim.x + threadIdx.x;
    if (i < n2) {
        float2 v = ((const float2*)src)[i];
        ((__half2*)dst)[i] = __floats2half2_rn(v.x, v.y);
    }
}

// attention over fp16 inputs -> fp16 mixed (v precomputed in g_buf)
__global__ void attn_h_kernel(const __half* __restrict__ c0p, const __half* __restrict__ c1p,
                              const __half* __restrict__ c2p, const __half* __restrict__ othp,
                              const float* __restrict__ v,
                              __half* __restrict__ out, int n_rows) {
    int w = (int)(((ll)blockIdx.x * blockDim.x + threadIdx.x) >> 5);
    if (w >= n_rows) return;
    int lane = threadIdx.x & 31;
    ll rb = (ll)w * DD;
    float2 c0 = __half22float2(((const __half2*)(c0p + rb))[lane]);
    float2 c1 = __half22float2(((const __half2*)(c1p + rb))[lane]);
    float2 c2 = __half22float2(((const __half2*)(c2p + rb))[lane]);
    float2 ot = __half22float2(((const __half2*)(othp + rb))[lane]);
    float2 vv = *(const float2*)(v + lane * 2);
    float w0 = warp_sum(c0.x * vv.x + c0.y * vv.y);
    float w1 = warp_sum(c1.x * vv.x + c1.y * vv.y);
    float w2 = warp_sum(c2.x * vv.x + c2.y * vv.y);
    float m = fmaxf(w0, fmaxf(w1, w2));
    float e0 = __expf(w0 - m), e1 = __expf(w1 - m), e2 = __expf(w2 - m);
    float inv = 1.f / (e0 + e1 + e2);
    float s0 = e0 * inv, s1 = e1 * inv, s2 = e2 * inv;
    float ox = 0.5f * (s0 * c0.x + s1 * c1.x + s2 * c2.x) + 0.5f * ot.x;
    float oy = 0.5f * (s0 * c0.y + s1 * c1.y + s2 * c2.y) + 0.5f * ot.y;
    ((__half2*)(out + rb))[lane] = __floats2half2_rn(ox, oy);
}

// final attention over fp32 accumulators -> fp32 out
__global__ void attn_f_kernel(const float* __restrict__ c0p, const float* __restrict__ c1p,
                              const float* __restrict__ c2p, const float* __restrict__ othp,
                              const float* __restrict__ v,
                              float* __restrict__ out, int n_rows) {
    int w = (int)(((ll)blockIdx.x * blockDim.x + threadIdx.x) >> 5);
    if (w >= n_rows) return;
    int lane = threadIdx.x & 31;
    ll base = (ll)w * DD + lane * 2;
    float2 c0 = *(const float2*)(c0p + base);
    float2 c1 = *(const float2*)(c1p + base);
    float2 c2 = *(const float2*)(c2p + base);
    float2 ot = *(const float2*)(othp + base);
    float2 vv = *(const float2*)(v + lane * 2);
    float w0 = warp_sum(c0.x * vv.x + c0.y * vv.y);
    float w1 = warp_sum(c1.x * vv.x + c1.y * vv.y);
    float w2 = warp_sum(c2.x * vv.x + c2.y * vv.y);
    float m = fmaxf(w0, fmaxf(w1, w2));
    float e0 = __expf(w0 - m), e1 = __expf(w1 - m), e2 = __expf(w2 - m);
    float inv = 1.f / (e0 + e1 + e2);
    float s0 = e0 * inv, s1 = e1 * inv, s2 = e2 * inv;
    float ox = (s0 * c0.x + s1 * c1.x + s2 * c2.x) + 0.5f * ot.x;
    float oy = (s0 * c0.y + s1 * c1.y + s2 * c2.y) + 0.5f * ot.y;
    *(float2*)(out + base) = make_float2(ox, oy);
}

// self-gating, float4 LDS inner loop; ONE gate per block (blockIdx.y = gate)
__global__ void gating_kernel(const float* __restrict__ in, const float* __restrict__ W,
                              const float* __restrict__ B, int n_rows,
                              float* o0, float* o1, float* o2, float* o3,
                              __half* h0, __half* h1, __half* h2, __half* h3) {
    __shared__ float sW[DD * DD];
    __shared__ float se[32 * DD];
    int g = blockIdx.y;
    int tx = threadIdx.x, ty = threadIdx.y;
    int tid = ty * 64 + tx;
    int row0 = blockIdx.x * 32;
    for (int i = tid; i < 32 * DD; i += 256) {
        int r = i >> 6, c = i & 63;
        int gr = row0 + r;
        se[i] = (gr < n_rows) ? in[(ll)gr * DD + c] : 0.f;
    }
    for (int i = tid; i < DD * DD; i += 256) sW[i] = W[(ll)g * DD * DD + i];
    __syncthreads();

    float* outs[4] = {o0, o1, o2, o3};
    __half* houts[4] = {h0, h1, h2, h3};
    float* og = outs[g];
    __half* hg = houts[g];

    float bg = B[g * DD + tx];
    float acc[8] = {0, 0, 0, 0, 0, 0, 0, 0};
#pragma unroll
    for (int d4 = 0; d4 < DD; d4 += 4) {
        float w0 = sW[(d4 + 0) * DD + tx];
        float w1 = sW[(d4 + 1) * DD + tx];
        float w2 = sW[(d4 + 2) * DD + tx];
        float w3 = sW[(d4 + 3) * DD + tx];
#pragma unroll
        for (int rr = 0; rr < 8; ++rr) {
            float4 s4 = *(const float4*)(se + (ty + 4 * rr) * DD + d4);
            acc[rr] = fmaf(s4.x, w0, acc[rr]);
            acc[rr] = fmaf(s4.y, w1, acc[rr]);
            acc[rr] = fmaf(s4.z, w2, acc[rr]);
            acc[rr] = fmaf(s4.w, w3, acc[rr]);
        }
    }
#pragma unroll
    for (int rr = 0; rr < 8; ++rr) {
        int r = ty + 4 * rr;
        int gr = row0 + r;
        if (gr < n_rows) {
            float z = acc[rr] + bg;
            float sig = 1.f / (1.f + __expf(-z));
            float ov = se[r * DD + tx] * sig;
            ll idx = (ll)gr * DD + tx;
            if (og) og[idx] = ov;
            if (hg) hg[idx] = __float2half(ov);
        }
    }
}

// ---------------------------------------------------------------------------
static inline int blocks_for(ll threads, int bs) { return (int)((threads + bs - 1) / bs); }

extern "C" void kernel_launch(void* const* d_in, const int* in_sizes, int n_in,
                              void* d_out, int out_size) {
    const float* user_emb  = (const float*)d_in[0];
    const float* item_emb  = (const float*)d_in[1];
    const float* gating_w  = (const float*)d_in[2];
    const float* gating_b  = (const float*)d_in[3];
    const float* sgating_w = (const float*)d_in[4];
    const float* sgating_b = (const float*)d_in[5];
    const float* att_mat   = (const float*)d_in[6];
    const float* att_agg   = (const float*)d_in[7];
    const int*   hs_row = (const int*)d_in[8];
    const int*   hs_col = (const int*)d_in[9];
    const float* hs_val = (const float*)d_in[10];
    const int*   hj_row = (const int*)d_in[11];
    const int*   hj_col = (const int*)d_in[12];
    const float* hj_val = (const float*)d_in[13];
    const int*   hp_row = (const int*)d_in[14];
    const int*   hp_col = (const int*)d_in[15];
    const float* hp_val = (const float*)d_in[16];
    const int*   inter_row = (const int*)d_in[17];
    const int*   inter_col = (const int*)d_in[18];
    const float* inter_val = (const float*)d_in[19];

    const int NNZ_H = in_sizes[8];
    const int NNZ_I = in_sizes[17];

    float* out = (float*)d_out;
    const ll O_ITEM = S;
    const ll O_SG0 = S + SI;
    const ll O_SG1 = 2 * S + SI;
    const ll O_SG2 = 3 * S + SI;

    float*  gb; cudaGetSymbolAddress((void**)&gb, g_buf);
    __half* gh; cudaGetSymbolAddress((void**)&gh, g_h);
    int*   off; cudaGetSymbolAddress((void**)&off, g_off);
    int*   cnt; cudaGetSymbolAddress((void**)&cnt, g_cnt);
    int*   rk;  cudaGetSymbolAddress((void**)&rk, g_rank);
    int2*  pr;  cudaGetSymbolAddress((void**)&pr, g_pair);

    static cudaStream_t sB = nullptr;
    static cudaEvent_t evRoot = nullptr, evB = nullptr;
    if (sB == nullptr) {
        cudaStreamCreateWithFlags(&sB, cudaStreamNonBlocking);
        cudaEventCreateWithFlags(&evRoot, cudaEventDisableTiming);
        cudaEventCreateWithFlags(&evB, cudaEventDisableTiming);
    }

    const int BS = 256;

    Build5 B;
    B.row[0] = hs_row;    B.col[0] = hs_col;    B.val[0] = hs_val;    B.nnz[0] = NNZ_H;
    B.row[1] = hj_row;    B.col[1] = hj_col;    B.val[1] = hj_val;    B.nnz[1] = NNZ_H;
    B.row[2] = hp_row;    B.col[2] = hp_col;    B.val[2] = hp_val;    B.nnz[2] = NNZ_H;
    B.row[3] = inter_row; B.col[3] = inter_col; B.val[3] = inter_val; B.nnz[3] = NNZ_I;
    B.row[4] = inter_col; B.col[4] = inter_row; B.val[4] = inter_val; B.nnz[4] = NNZ_I;
    ll po = 0, ro = 0;
    for (int m = 0; m < 5; ++m) {
        B.cnt[m] = cnt + m * (NU + 1);
        B.off[m] = off + m * (NU + 1);
        B.pair[m] = pr + po;  po += B.nnz[m];
        B.rank[m] = rk + ro;  ro += B.nnz[m];
    }

    // fork: build branch runs on sB concurrently with the dense prologue
    cudaEventRecord(evRoot, 0);
    cudaStreamWaitEvent(sB, evRoot, 0);

    // ---- branch B (side stream): CSR build ----
    int bpr = blocks_for((NNZ_H + 3) / 4, BS);
    zero_int_kernel<<<blocks_for(OFFLEN, BS), BS, 0, sB>>>(cnt, OFFLEN);
    hist5_kernel<<<5 * bpr, BS, 0, sB>>>(B, bpr);
    scan_kernel<<<5, 1024, 0, sB>>>();
    scat5_kernel<<<5 * bpr, BS, 0, sB>>>(B, bpr);
    cudaEventRecord(evB, sB);

    // ---- branch A (default stream): dense prologue ----
    compute_v_kernel<<<1, 64>>>(att_mat, att_agg);
    item_h_kernel<<<blocks_for(SI / 2, BS), BS>>>(item_emb, gh + XIT, (int)(SI / 2));
    cudaMemcpyAsync(out + O_ITEM, item_emb, SI * sizeof(float), cudaMemcpyDeviceToDevice, 0);

    dim3 gdim(64, 4);
    dim3 ggrid4((NU + 31) / 32, 4);
    gating_kernel<<<ggrid4, gdim>>>(user_emb, gating_w, gating_b, NU,
                                    gb + ACC0, gb + ACC1, gb + ACC2, gb + ACCS,
                                    gh + XG0, gh + XG1, gh + XG2, gh + XGS);

    const int uwb = blocks_for((ll)NU * 32, BS);
    attn_h_kernel<<<uwb, BS>>>(gh + XG0, gh + XG1, gh + XG2, gh + XGS, gb + VOFF,
                               gh + XMIX, NU);

    // join: SpMM needs both branches
    cudaStreamWaitEvent(0, evB, 0);

    const ll TOTW = 4ll * NU + NI;
    const int swb = blocks_for(TOTW * 32, BS);

    // ---- layer 1 ----
    Spmm5 A1;
    A1.off[0] = B.off[0]; A1.pair[0] = B.pair[0]; A1.x[0] = gh + XG0; A1.y[0] = gh + XT0; A1.acc[0] = gb + ACC0;
    A1.off[1] = B.off[1]; A1.pair[1] = B.pair[1]; A1.x[1] = gh + XG1; A1.y[1] = gh + XT1; A1.acc[1] = gb + ACC1;
    A1.off[2] = B.off[2]; A1.pair[2] = B.pair[2]; A1.x[2] = gh + XG2; A1.y[2] = gh + XT2; A1.acc[2] = gb + ACC2;
    A1.off[3] = B.off[4]; A1.pair[3] = B.pair[4]; A1.x[3] = gh + XMIX; A1.y[3] = gh + XITA; A1.acc[3] = out + O_ITEM;
    A1.off[4] = B.off[3]; A1.pair[4] = B.pair[3]; A1.x[4] = gh + XIT; A1.y[4] = gh + XUS; A1.acc[4] = gb + ACCS;
    spmm5_kernel<<<swb, BS>>>(A1);

    // ---- layer 2 ----
    attn_h_kernel<<<uwb, BS>>>(gh + XT0, gh + XT1, gh + XT2, gh + XUS, gb + VOFF,
                               gh + XMIX, NU);
    Spmm5 A2;
    A2.off[0] = B.off[0]; A2.pair[0] = B.pair[0]; A2.x[0] = gh + XT0; A2.y[0] = nullptr; A2.acc[0] = gb + ACC0;
    A2.off[1] = B.off[1]; A2.pair[1] = B.pair[1]; A2.x[1] = gh + XT1; A2.y[1] = nullptr; A2.acc[1] = gb + ACC1;
    A2.off[2] = B.off[2]; A2.pair[2] = B.pair[2]; A2.x[2] = gh + XT2; A2.y[2] = nullptr; A2.acc[2] = gb + ACC2;
    A2.off[3] = B.off[4]; A2.pair[3] = B.pair[4]; A2.x[3] = gh + XMIX; A2.y[3] = nullptr; A2.acc[3] = out + O_ITEM;
    A2.off[4] = B.off[3]; A2.pair[4] = B.pair[3]; A2.x[4] = gh + XITA; A2.y[4] = nullptr; A2.acc[4] = gb + ACCS;
    spmm5_kernel<<<swb, BS>>>(A2);

    // ---- final ----
    attn_f_kernel<<<uwb, BS>>>(gb + ACC0, gb + ACC1, gb + ACC2, gb + ACCS, gb + VOFF,
                               out, NU);
    dim3 ggrid3((NU + 31) / 32, 3);
    gating_kernel<<<ggrid3, gdim>>>(out, sgating_w, sgating_b, NU,
                                    out + O_SG0, out + O_SG1, out + O_SG2, nullptr,
                                    nullptr, nullptr, nullptr, nullptr);
}

// round 15
// speedup vs baseline: 1.0561x; 1.0561x over previous
#include <cuda_runtime.h>
#include <cuda_fp16.h>
#include <math.h>

#define NU 100000
#define NI 50000
#define DD 64
#define EPSV 1e-12f
#define MAXH 3200000
#define MAXI 3000000

typedef long long ll;

static constexpr ll S  = (ll)NU * DD;
static constexpr ll SI = (ll)NI * DD;

// fp32 scratch: 4 accumulators + v vector
static constexpr ll ACC0 = 0;
static constexpr ll ACC1 = 1 * S;
static constexpr ll ACC2 = 2 * S;
static constexpr ll ACCS = 3 * S;
static constexpr ll VOFF = 4 * S;
static constexpr ll TOT32 = VOFF + 64;
__device__ float g_buf[TOT32];

// fp16 gather-format scratch
static constexpr ll XG0 = 0;
static constexpr ll XG1 = 1 * S;
static constexpr ll XG2 = 2 * S;
static constexpr ll XGS = 3 * S;
static constexpr ll XT0 = 4 * S;
static constexpr ll XT1 = 5 * S;
static constexpr ll XT2 = 6 * S;
static constexpr ll XUS = 7 * S;
static constexpr ll XMIX = 8 * S;
static constexpr ll XIT  = 9 * S;
static constexpr ll XITA = 9 * S + SI;
static constexpr ll TOT16 = 9 * S + 2 * SI;
__device__ __half g_h[TOT16];

// CSR scratch
static constexpr int OFFLEN = 4 * (NU + 1) + (NI + 1);
__device__ int  g_off[OFFLEN];
__device__ int  g_cnt[OFFLEN];
__device__ int  g_rank[3 * (ll)MAXH + 2 * (ll)MAXI];
__device__ int2 g_pair[3 * (ll)MAXH + 2 * (ll)MAXI];

struct Build5 {
    const int* row[5]; const int* col[5]; const float* val[5];
    int* rank[5]; int* cnt[5]; const int* off[5]; int2* pair[5]; int nnz[5];
};
struct Spmm5 { const int* off[5]; const int2* pair[5];
               const __half* x[5]; __half* y[5]; float* acc[5]; };

// ---------------------------------------------------------------------------
__device__ __forceinline__ float warp_sum(float v) {
#pragma unroll
    for (int o = 16; o > 0; o >>= 1) v += __shfl_xor_sync(0xFFFFFFFFu, v, o);
    return v;
}

// ---------------------------------------------------------------------------
__global__ void zero_int_kernel(int* p, int n) {
    int i = blockIdx.x * blockDim.x + threadIdx.x;
    if (i < n) p[i] = 0;
}

// fused 5-region histogram, 4 edges/thread, stores per-edge rank
__global__ void hist5_kernel(Build5 b, int bpr) {
    int region = blockIdx.x / bpr;
    int bb = blockIdx.x - region * bpr;
    int nnz = b.nnz[region];
    const int* __restrict__ row = b.row[region];
    int* __restrict__ rank = b.rank[region];
    int* cnt = b.cnt[region];
    int i = (bb * 256 + threadIdx.x) * 4;
    if (i + 3 < nnz) {
        int4 r = *(const int4*)(row + i);
        int k0 = atomicAdd(cnt + r.x, 1);
        int k1 = atomicAdd(cnt + r.y, 1);
        int k2 = atomicAdd(cnt + r.z, 1);
        int k3 = atomicAdd(cnt + r.w, 1);
        *(int4*)(rank + i) = make_int4(k0, k1, k2, k3);
    } else {
        for (int j = i; j < nnz; ++j) rank[j] = atomicAdd(cnt + __ldg(row + j), 1);
    }
}

// one block per region; chunked exclusive scan of counts -> off
__global__ void scan_kernel() {
    int region = blockIdx.x;
    int n = (region == 4) ? NI : NU;
    int base = region * (NU + 1);
    int* cnt = g_cnt + base;
    int* off = g_off + base;
    const int T = 1024;
    int t = threadIdx.x;
    int chunk = (n + T - 1) / T;
    int lo = t * chunk;
    int hi = lo + chunk; if (hi > n) hi = n;
    int sum = 0;
    for (int i = lo; i < hi; ++i) sum += cnt[i];

    __shared__ int ws[32];
    int lane = t & 31, wid = t >> 5;
    int x = sum;
#pragma unroll
    for (int o = 1; o < 32; o <<= 1) {
        int y = __shfl_up_sync(0xFFFFFFFFu, x, o);
        if (lane >= o) x += y;
    }
    if (lane == 31) ws[wid] = x;
    __syncthreads();
    if (t < 32) {
        int y = ws[t];
#pragma unroll
        for (int o = 1; o < 32; o <<= 1) {
            int z = __shfl_up_sync(0xFFFFFFFFu, y, o);
            if (t >= o) y += z;
        }
        ws[t] = y;
    }
    __syncthreads();
    int pre = x - sum + ((wid > 0) ? ws[wid - 1] : 0);
    if (t == T - 1) off[n] = pre + sum;
    int run = pre;
    for (int i = lo; i < hi; ++i) {
        int v = cnt[i];
        off[i] = run;
        run += v;
    }
}

// fused 5-region scatter, 4 edges/thread, atomic-free via rank
__global__ void scat5_kernel(Build5 b, int bpr) {
    int region = blockIdx.x / bpr;
    int bb = blockIdx.x - region * bpr;
    int nnz = b.nnz[region];
    const int* __restrict__ row = b.row[region];
    const int* __restrict__ col = b.col[region];
    const float* __restrict__ val = b.val[region];
    const int* __restrict__ rank = b.rank[region];
    const int* __restrict__ off = b.off[region];
    int2* __restrict__ pair = b.pair[region];
    int i = (bb * 256 + threadIdx.x) * 4;
    if (i + 3 < nnz) {
        int4 r = *(const int4*)(row + i);
        int4 c = *(const int4*)(col + i);
        float4 v = *(const float4*)(val + i);
        int4 k = *(const int4*)(rank + i);
        pair[__ldg(off + r.x) + k.x] = make_int2(c.x, __float_as_int(v.x));
        pair[__ldg(off + r.y) + k.y] = make_int2(c.y, __float_as_int(v.y));
        pair[__ldg(off + r.z) + k.z] = make_int2(c.z, __float_as_int(v.z));
        pair[__ldg(off + r.w) + k.w] = make_int2(c.w, __float_as_int(v.w));
    } else {
        for (int j = i; j < nnz; ++j) {
            pair[__ldg(off + __ldg(row + j)) + __ldg(rank + j)] =
                make_int2(__ldg(col + j), __float_as_int(__ldg(val + j)));
        }
    }
}

// Fused 5-region CSR SpMM: one warp per row, cooperative pair loading via shfl,
// fp16 gathers, fp32 accumulate, fused l2norm-acc.
__global__ void spmm5_kernel(Spmm5 a) {
    ll gw = ((ll)blockIdx.x * blockDim.x + threadIdx.x) >> 5;
    int lane = threadIdx.x & 31;
    int region, row;
    if (gw < NU)                { region = 0; row = (int)gw; }
    else if (gw < 2 * NU)       { region = 1; row = (int)(gw - NU); }
    else if (gw < 3 * NU)       { region = 2; row = (int)(gw - 2 * NU); }
    else if (gw < 3 * NU + NI)  { region = 3; row = (int)(gw - 3 * NU); }
    else if (gw < 4 * NU + NI)  { region = 4; row = (int)(gw - 3 * NU - NI); }
    else return;

    const int* off = a.off[region];
    const int2* __restrict__ pair = a.pair[region];
    const __half* __restrict__ x16 = a.x[region];
    int s = __ldg(off + row), e = __ldg(off + row + 1);
    float ax = 0.f, ay = 0.f;
    int base = s;
    while (e - base >= 32) {
        int2 myp = __ldg(pair + base + lane);
#pragma unroll 8
        for (int j = 0; j < 32; ++j) {
            int c = __shfl_sync(0xFFFFFFFFu, myp.x, j);
            float v = __int_as_float(__shfl_sync(0xFFFFFFFFu, myp.y, j));
            float2 f = __half22float2(__ldg((const __half2*)(x16 + (ll)c * DD) + lane));
            ax = fmaf(v, f.x, ax); ay = fmaf(v, f.y, ay);
        }
        base += 32;
    }
    int rem = e - base;
    if (rem > 0) {
        int2 myp = (lane < rem) ? __ldg(pair + base + lane) : make_int2(0, 0);
        for (int j = 0; j < rem; ++j) {
            int c = __shfl_sync(0xFFFFFFFFu, myp.x, j);
            float v = __int_as_float(__shfl_sync(0xFFFFFFFFu, myp.y, j));
            float2 f = __half22float2(__ldg((const __half2*)(x16 + (ll)c * DD) + lane));
            ax = fmaf(v, f.x, ax); ay = fmaf(v, f.y, ay);
        }
    }

    __half* y16 = a.y[region];
    if (y16) ((__half2*)(y16 + (ll)row * DD))[lane] = __floats2half2_rn(ax, ay);
    float ss = warp_sum(ax * ax + ay * ay);
    float sc = 1.f / fmaxf(sqrtf(ss), EPSV);
    float* acc = a.acc[region];
    ll b2 = (ll)row * DD + lane * 2;
    float2 av = *(const float2*)(acc + b2);
    av.x = fmaf(ax, sc, av.x);
    av.y = fmaf(ay, sc, av.y);
    *(float2*)(acc + b2) = av;
}

// v[d] = sum_j att_mat[d][j] * att_agg[j]
__global__ void compute_v_kernel(const float* __restrict__ att_mat,
                                 const float* __restrict__ att_agg) {
    int d = threadIdx.x;
    float s = 0.f;
#pragma unroll
    for (int j = 0; j < DD; ++j) s = fmaf(att_mat[d * DD + j], att_agg[j], s);
    g_buf[VOFF + d] = s;
}

__global__ void item_h_kernel(const float* __restrict__ src, __half* __restrict__ dst, int n2) {
    int i = blockIdx.x * blockDim.x + threadIdx.x;
    if (i < n2) {
        float2 v = ((const float2*)src)[i];
        ((__half2*)dst)[i] = __floats2half2_rn(v.x, v.y);
    }
}

// attention over fp16 inputs -> fp16 mixed (v precomputed in g_buf)
__global__ void attn_h_kernel(const __half* __restrict__ c0p, const __half* __restrict__ c1p,
                              const __half* __restrict__ c2p, const __half* __restrict__ othp,
                              const float* __restrict__ v,
                              __half* __restrict__ out, int n_rows) {
    int w = (int)(((ll)blockIdx.x * blockDim.x + threadIdx.x) >> 5);
    if (w >= n_rows) return;
    int lane = threadIdx.x & 31;
    ll rb = (ll)w * DD;
    float2 c0 = __half22float2(((const __half2*)(c0p + rb))[lane]);
    float2 c1 = __half22float2(((const __half2*)(c1p + rb))[lane]);
    float2 c2 = __half22float2(((const __half2*)(c2p + rb))[lane]);
    float2 ot = __half22float2(((const __half2*)(othp + rb))[lane]);
    float2 vv = *(const float2*)(v + lane * 2);
    float w0 = warp_sum(c0.x * vv.x + c0.y * vv.y);
    float w1 = warp_sum(c1.x * vv.x + c1.y * vv.y);
    float w2 = warp_sum(c2.x * vv.x + c2.y * vv.y);
    float m = fmaxf(w0, fmaxf(w1, w2));
    float e0 = __expf(w0 - m), e1 = __expf(w1 - m), e2 = __expf(w2 - m);
    float inv = 1.f / (e0 + e1 + e2);
    float s0 = e0 * inv, s1 = e1 * inv, s2 = e2 * inv;
    float ox = 0.5f * (s0 * c0.x + s1 * c1.x + s2 * c2.x) + 0.5f * ot.x;
    float oy = 0.5f * (s0 * c0.y + s1 * c1.y + s2 * c2.y) + 0.5f * ot.y;
    ((__half2*)(out + rb))[lane] = __floats2half2_rn(ox, oy);
}

// final attention over fp32 accumulators -> fp32 out
__global__ void attn_f_kernel(const float* __restrict__ c0p, const float* __restrict__ c1p,
                              const float* __restrict__ c2p, const float* __restrict__ othp,
                              const float* __restrict__ v,
                              float* __restrict__ out, int n_rows) {
    int w = (int)(((ll)blockIdx.x * blockDim.x + threadIdx.x) >> 5);
    if (w >= n_rows) return;
    int lane = threadIdx.x & 31;
    ll base = (ll)w * DD + lane * 2;
    float2 c0 = *(const float2*)(c0p + base);
    float2 c1 = *(const float2*)(c1p + base);
    float2 c2 = *(const float2*)(c2p + base);
    float2 ot = *(const float2*)(othp + base);
    float2 vv = *(const float2*)(v + lane * 2);
    float w0 = warp_sum(c0.x * vv.x + c0.y * vv.y);
    float w1 = warp_sum(c1.x * vv.x + c1.y * vv.y);
    float w2 = warp_sum(c2.x * vv.x + c2.y * vv.y);
    float m = fmaxf(w0, fmaxf(w1, w2));
    float e0 = __expf(w0 - m), e1 = __expf(w1 - m), e2 = __expf(w2 - m);
    float inv = 1.f / (e0 + e1 + e2);
    float s0 = e0 * inv, s1 = e1 * inv, s2 = e2 * inv;
    float ox = (s0 * c0.x + s1 * c1.x + s2 * c2.x) + 0.5f * ot.x;
    float oy = (s0 * c0.y + s1 * c1.y + s2 * c2.y) + 0.5f * ot.y;
    *(float2*)(out + base) = make_float2(ox, oy);
}

// self-gating, float4 LDS inner loop; ONE gate per block (blockIdx.y = gate)
__global__ void gating_kernel(const float* __restrict__ in, const float* __restrict__ W,
                              const float* __restrict__ B, int n_rows,
                              float* o0, float* o1, float* o2, float* o3,
                              __half* h0, __half* h1, __half* h2, __half* h3) {
    __shared__ float sW[DD * DD];
    __shared__ float se[32 * DD];
    int g = blockIdx.y;
    int tx = threadIdx.x, ty = threadIdx.y;
    int tid = ty * 64 + tx;
    int row0 = blockIdx.x * 32;
    for (int i = tid; i < 32 * DD; i += 256) {
        int r = i >> 6, c = i & 63;
        int gr = row0 + r;
        se[i] = (gr < n_rows) ? in[(ll)gr * DD + c] : 0.f;
    }
    for (int i = tid; i < DD * DD; i += 256) sW[i] = W[(ll)g * DD * DD + i];
    __syncthreads();

    float* outs[4] = {o0, o1, o2, o3};
    __half* houts[4] = {h0, h1, h2, h3};
    float* og = outs[g];
    __half* hg = houts[g];

    float bg = B[g * DD + tx];
    float acc[8] = {0, 0, 0, 0, 0, 0, 0, 0};
#pragma unroll
    for (int d4 = 0; d4 < DD; d4 += 4) {
        float w0 = sW[(d4 + 0) * DD + tx];
        float w1 = sW[(d4 + 1) * DD + tx];
        float w2 = sW[(d4 + 2) * DD + tx];
        float w3 = sW[(d4 + 3) * DD + tx];
#pragma unroll
        for (int rr = 0; rr < 8; ++rr) {
            float4 s4 = *(const float4*)(se + (ty + 4 * rr) * DD + d4);
            acc[rr] = fmaf(s4.x, w0, acc[rr]);
            acc[rr] = fmaf(s4.y, w1, acc[rr]);
            acc[rr] = fmaf(s4.z, w2, acc[rr]);
            acc[rr] = fmaf(s4.w, w3, acc[rr]);
        }
    }
#pragma unroll
    for (int rr = 0; rr < 8; ++rr) {
        int r = ty + 4 * rr;
        int gr = row0 + r;
        if (gr < n_rows) {
            float z = acc[rr] + bg;
            float sig = 1.f / (1.f + __expf(-z));
            float ov = se[r * DD + tx] * sig;
            ll idx = (ll)gr * DD + tx;
            if (og) og[idx] = ov;
            if (hg) hg[idx] = __float2half(ov);
        }
    }
}

// ---------------------------------------------------------------------------
static inline int blocks_for(ll threads, int bs) { return (int)((threads + bs - 1) / bs); }

extern "C" void kernel_launch(void* const* d_in, const int* in_sizes, int n_in,
                              void* d_out, int out_size) {
    const float* user_emb  = (const float*)d_in[0];
    const float* item_emb  = (const float*)d_in[1];
    const float* gating_w  = (const float*)d_in[2];
    const float* gating_b  = (const float*)d_in[3];
    const float* sgating_w = (const float*)d_in[4];
    const float* sgating_b = (const float*)d_in[5];
    const float* att_mat   = (const float*)d_in[6];
    const float* att_agg   = (const float*)d_in[7];
    const int*   hs_row = (const int*)d_in[8];
    const int*   hs_col = (const int*)d_in[9];
    const float* hs_val = (const float*)d_in[10];
    const int*   hj_row = (const int*)d_in[11];
    const int*   hj_col = (const int*)d_in[12];
    const float* hj_val = (const float*)d_in[13];
    const int*   hp_row = (const int*)d_in[14];
    const int*   hp_col = (const int*)d_in[15];
    const float* hp_val = (const float*)d_in[16];
    const int*   inter_row = (const int*)d_in[17];
    const int*   inter_col = (const int*)d_in[18];
    const float* inter_val = (const float*)d_in[19];

    const int NNZ_H = in_sizes[8];
    const int NNZ_I = in_sizes[17];

    float* out = (float*)d_out;
    const ll O_ITEM = S;
    const ll O_SG0 = S + SI;
    const ll O_SG1 = 2 * S + SI;
    const ll O_SG2 = 3 * S + SI;

    float*  gb; cudaGetSymbolAddress((void**)&gb, g_buf);
    __half* gh; cudaGetSymbolAddress((void**)&gh, g_h);
    int*   off; cudaGetSymbolAddress((void**)&off, g_off);
    int*   cnt; cudaGetSymbolAddress((void**)&cnt, g_cnt);
    int*   rk;  cudaGetSymbolAddress((void**)&rk, g_rank);
    int2*  pr;  cudaGetSymbolAddress((void**)&pr, g_pair);

    static cudaStream_t sB = nullptr;
    static cudaEvent_t evRoot = nullptr, evB = nullptr;
    if (sB == nullptr) {
        cudaStreamCreateWithFlags(&sB, cudaStreamNonBlocking);
        cudaEventCreateWithFlags(&evRoot, cudaEventDisableTiming);
        cudaEventCreateWithFlags(&evB, cudaEventDisableTiming);
    }

    const int BS = 256;

    Build5 B;
    B.row[0] = hs_row;    B.col[0] = hs_col;    B.val[0] = hs_val;    B.nnz[0] = NNZ_H;
    B.row[1] = hj_row;    B.col[1] = hj_col;    B.val[1] = hj_val;    B.nnz[1] = NNZ_H;
    B.row[2] = hp_row;    B.col[2] = hp_col;    B.val[2] = hp_val;    B.nnz[2] = NNZ_H;
    B.row[3] = inter_row; B.col[3] = inter_col; B.val[3] = inter_val; B.nnz[3] = NNZ_I;
    B.row[4] = inter_col; B.col[4] = inter_row; B.val[4] = inter_val; B.nnz[4] = NNZ_I;
    ll po = 0, ro = 0;
    for (int m = 0; m < 5; ++m) {
        B.cnt[m] = cnt + m * (NU + 1);
        B.off[m] = off + m * (NU + 1);
        B.pair[m] = pr + po;  po += B.nnz[m];
        B.rank[m] = rk + ro;  ro += B.nnz[m];
    }

    // fork: build branch runs on sB concurrently with the dense prologue
    cudaEventRecord(evRoot, 0);
    cudaStreamWaitEvent(sB, evRoot, 0);

    // ---- branch B (side stream): CSR build ----
    int bpr = blocks_for((NNZ_H + 3) / 4, BS);
    zero_int_kernel<<<blocks_for(OFFLEN, BS), BS, 0, sB>>>(cnt, OFFLEN);
    hist5_kernel<<<5 * bpr, BS, 0, sB>>>(B, bpr);
    scan_kernel<<<5, 1024, 0, sB>>>();
    scat5_kernel<<<5 * bpr, BS, 0, sB>>>(B, bpr);
    cudaEventRecord(evB, sB);

    // ---- branch A (default stream): dense prologue ----
    compute_v_kernel<<<1, 64>>>(att_mat, att_agg);
    item_h_kernel<<<blocks_for(SI / 2, BS), BS>>>(item_emb, gh + XIT, (int)(SI / 2));
    cudaMemcpyAsync(out + O_ITEM, item_emb, SI * sizeof(float), cudaMemcpyDeviceToDevice, 0);

    dim3 gdim(64, 4);
    dim3 ggrid4((NU + 31) / 32, 4);
    gating_kernel<<<ggrid4, gdim>>>(user_emb, gating_w, gating_b, NU,
                                    gb + ACC0, gb + ACC1, gb + ACC2, gb + ACCS,
                                    gh + XG0, gh + XG1, gh + XG2, gh + XGS);

    const int uwb = blocks_for((ll)NU * 32, BS);
    attn_h_kernel<<<uwb, BS>>>(gh + XG0, gh + XG1, gh + XG2, gh + XGS, gb + VOFF,
                               gh + XMIX, NU);

    // join: SpMM needs both branches
    cudaStreamWaitEvent(0, evB, 0);

    const ll TOTW = 4ll * NU + NI;
    const int swb = blocks_for(TOTW * 32, BS);

    // ---- layer 1 ----
    Spmm5 A1;
    A1.off[0] = B.off[0]; A1.pair[0] = B.pair[0]; A1.x[0] = gh + XG0; A1.y[0] = gh + XT0; A1.acc[0] = gb + ACC0;
    A1.off[1] = B.off[1]; A1.pair[1] = B.pair[1]; A1.x[1] = gh + XG1; A1.y[1] = gh + XT1; A1.acc[1] = gb + ACC1;
    A1.off[2] = B.off[2]; A1.pair[2] = B.pair[2]; A1.x[2] = gh + XG2; A1.y[2] = gh + XT2; A1.acc[2] = gb + ACC2;
    A1.off[3] = B.off[4]; A1.pair[3] = B.pair[4]; A1.x[3] = gh + XMIX; A1.y[3] = gh + XITA; A1.acc[3] = out + O_ITEM;
    A1.off[4] = B.off[3]; A1.pair[4] = B.pair[3]; A1.x[4] = gh + XIT; A1.y[4] = gh + XUS; A1.acc[4] = gb + ACCS;
    spmm5_kernel<<<swb, BS>>>(A1);

    // ---- layer 2 ----
    attn_h_kernel<<<uwb, BS>>>(gh + XT0, gh + XT1, gh + XT2, gh + XUS, gb + VOFF,
                               gh + XMIX, NU);
    Spmm5 A2;
    A2.off[0] = B.off[0]; A2.pair[0] = B.pair[0]; A2.x[0] = gh + XT0; A2.y[0] = nullptr; A2.acc[0] = gb + ACC0;
    A2.off[1] = B.off[1]; A2.pair[1] = B.pair[1]; A2.x[1] = gh + XT1; A2.y[1] = nullptr; A2.acc[1] = gb + ACC1;
    A2.off[2] = B.off[2]; A2.pair[2] = B.pair[2]; A2.x[2] = gh + XT2; A2.y[2] = nullptr; A2.acc[2] = gb + ACC2;
    A2.off[3] = B.off[4]; A2.pair[3] = B.pair[4]; A2.x[3] = gh + XMIX; A2.y[3] = nullptr; A2.acc[3] = out + O_ITEM;
    A2.off[4] = B.off[3]; A2.pair[4] = B.pair[3]; A2.x[4] = gh + XITA; A2.y[4] = nullptr; A2.acc[4] = gb + ACCS;
    spmm5_kernel<<<swb, BS>>>(A2);

    // ---- final ----
    attn_f_kernel<<<uwb, BS>>>(gb + ACC0, gb + ACC1, gb + ACC2, gb + ACCS, gb + VOFF,
                               out, NU);
    dim3 ggrid3((NU + 31) / 32, 3);
    gating_kernel<<<ggrid3, gdim>>>(out, sgating_w, sgating_b, NU,
                                    out + O_SG0, out + O_SG1, out + O_SG2, nullptr,
                                    nullptr, nullptr, nullptr, nullptr);
}